// round 2
// baseline (speedup 1.0000x reference)
#include <cuda_runtime.h>
#include <cstdint>

#define D 128
#define MAX_NODES 20000

// Scratch (allocation-free). 16B alignment required for red.global.add.v4.f32.
__device__ __align__(16) float g_T[MAX_NODES * D];
__device__ __align__(16) float g_H[MAX_NODES * D];
__device__ int g_is64;   // 1 if edge_index buffer is int64, 0 if int32

// ----------------------------------------------------------------------------
// Detect edge_index dtype. If int64 with values < 2^31, every odd 32-bit word
// (the high half) is zero. If int32, odd words are random node indices.
// Deterministic; runs every call.
// ----------------------------------------------------------------------------
__global__ void detect_dtype(const unsigned int* __restrict__ w)
{
    __shared__ int any;
    if (threadIdx.x == 0) any = 0;
    __syncthreads();
    int found = 0;
    for (int i = threadIdx.x; i < 2048; i += blockDim.x)
        if (w[2 * i + 1] != 0u) found = 1;
    if (found) atomicOr(&any, 1);
    __syncthreads();
    if (threadIdx.x == 0) g_is64 = any ? 0 : 1;
}

// ----------------------------------------------------------------------------
// Dual GEMM: C_y = act(A) @ W_y (+ bias for y==1), where y = blockIdx.y
// A: [M,128] row-major, W: [128,128] row-major. Tile: BM=128, BN=128, BK=32.
// 256 threads, each computes an 8x8 micro-tile.
// ----------------------------------------------------------------------------
template <bool RELU>
__global__ __launch_bounds__(256) void gemm_dual(
    const float* __restrict__ A,
    const float* __restrict__ Wrel,
    const float* __restrict__ Wroot,
    const float* __restrict__ bias,   // applied only for y==1
    float* __restrict__ Trel,
    float* __restrict__ Hout,
    int M)
{
    const float* __restrict__ W = blockIdx.y ? Wroot : Wrel;
    float* __restrict__ C       = blockIdx.y ? Hout  : Trel;

    __shared__ float As[32][132];   // As[k][m] (transposed, padded)
    __shared__ float Bs[32][128];   // Bs[k][n]

    const int tid = threadIdx.x;
    const int tx  = tid & 15;        // n-dir
    const int ty  = tid >> 4;        // m-dir
    const int tm  = ty * 8;
    const int tn  = tx * 8;
    const int m0  = blockIdx.x * 128;

    float acc[8][8];
#pragma unroll
    for (int i = 0; i < 8; i++)
#pragma unroll
        for (int j = 0; j < 8; j++) acc[i][j] = 0.0f;

    for (int k0 = 0; k0 < D; k0 += 32) {
        // ---- load A tile 128x32 (transposed into As[k][m]), optional ReLU ----
#pragma unroll
        for (int it = 0; it < 4; it++) {
            int f   = tid + it * 256;          // float4 index in [0,1024)
            int row = f >> 3;                  // 8 float4 per row
            int c4  = f & 7;
            float4 v = make_float4(0.f, 0.f, 0.f, 0.f);
            int grow = m0 + row;
            if (grow < M)
                v = *reinterpret_cast<const float4*>(A + (size_t)grow * D + k0 + c4 * 4);
            if (RELU) {
                v.x = fmaxf(v.x, 0.f); v.y = fmaxf(v.y, 0.f);
                v.z = fmaxf(v.z, 0.f); v.w = fmaxf(v.w, 0.f);
            }
            As[c4 * 4 + 0][row] = v.x;
            As[c4 * 4 + 1][row] = v.y;
            As[c4 * 4 + 2][row] = v.z;
            As[c4 * 4 + 3][row] = v.w;
        }
        // ---- load W tile 32x128 (direct) ----
#pragma unroll
        for (int it = 0; it < 4; it++) {
            int f    = tid + it * 256;         // float4 index in [0,1024)
            int krow = f >> 5;                 // 32 float4 per row
            int c4   = f & 31;
            float4 v = *reinterpret_cast<const float4*>(W + (size_t)(k0 + krow) * D + c4 * 4);
            *reinterpret_cast<float4*>(&Bs[krow][c4 * 4]) = v;
        }
        __syncthreads();

        // ---- compute ----
#pragma unroll
        for (int k = 0; k < 32; k++) {
            float a[8], b[8];
            *reinterpret_cast<float4*>(&a[0]) = *reinterpret_cast<const float4*>(&As[k][tm]);
            *reinterpret_cast<float4*>(&a[4]) = *reinterpret_cast<const float4*>(&As[k][tm + 4]);
            *reinterpret_cast<float4*>(&b[0]) = *reinterpret_cast<const float4*>(&Bs[k][tn]);
            *reinterpret_cast<float4*>(&b[4]) = *reinterpret_cast<const float4*>(&Bs[k][tn + 4]);
#pragma unroll
            for (int i = 0; i < 8; i++)
#pragma unroll
                for (int j = 0; j < 8; j++)
                    acc[i][j] = fmaf(a[i], b[j], acc[i][j]);
        }
        __syncthreads();
    }

    // ---- epilogue: bias for root half, store ----
    float bv[8];
#pragma unroll
    for (int j = 0; j < 8; j++) bv[j] = blockIdx.y ? bias[tn + j] : 0.0f;

#pragma unroll
    for (int i = 0; i < 8; i++) {
        int row = m0 + tm + i;
        if (row < M) {
            float4 o0, o1;
            o0.x = acc[i][0] + bv[0]; o0.y = acc[i][1] + bv[1];
            o0.z = acc[i][2] + bv[2]; o0.w = acc[i][3] + bv[3];
            o1.x = acc[i][4] + bv[4]; o1.y = acc[i][5] + bv[5];
            o1.z = acc[i][6] + bv[6]; o1.w = acc[i][7] + bv[7];
            *reinterpret_cast<float4*>(C + (size_t)row * D + tn)     = o0;
            *reinterpret_cast<float4*>(C + (size_t)row * D + tn + 4) = o1;
        }
    }
}

// ----------------------------------------------------------------------------
// Edge scatter: H[dst] += T[src], warp per edge, lane owns a float4 chunk.
// Vector L2 reduction (red.global.add.v4.f32): non-blocking, no return.
// Index dtype resolved at runtime via g_is64.
// ----------------------------------------------------------------------------
__global__ __launch_bounds__(256) void scatter_add(
    const float* __restrict__ T,
    const void* __restrict__ ei_raw,   // [2, E]: row0=src, row1=dst (int32 or int64)
    float* __restrict__ H,
    int E)
{
    const int warp  = (blockIdx.x * blockDim.x + threadIdx.x) >> 5;
    const int nwarp = (gridDim.x * blockDim.x) >> 5;
    const int off   = (threadIdx.x & 31) * 4;
    const int is64  = g_is64;
    const int*       ei32 = (const int*)ei_raw;
    const long long* ei64 = (const long long*)ei_raw;

    for (int e = warp; e < E; e += nwarp) {
        int src, dst;
        if (is64) {
            src = (int)ei64[e];
            dst = (int)ei64[E + e];
        } else {
            src = ei32[e];
            dst = ei32[E + e];
        }
        const float4 v = *reinterpret_cast<const float4*>(T + (size_t)src * D + off);
        float* p = H + (size_t)dst * D + off;
        asm volatile("red.global.add.v4.f32 [%0], {%1, %2, %3, %4};"
                     :: "l"(p), "f"(v.x), "f"(v.y), "f"(v.z), "f"(v.w)
                     : "memory");
    }
}

// ----------------------------------------------------------------------------
// kernel_launch
// Inputs (metadata order): x, edge_index, W1_rel, b1_rel, W1_root,
//                          W2_rel, b2_rel, W2_root
// ----------------------------------------------------------------------------
extern "C" void kernel_launch(void* const* d_in, const int* in_sizes, int n_in,
                              void* d_out, int out_size)
{
    const float* x       = (const float*)d_in[0];
    const void*  ei      = d_in[1];
    const float* W1_rel  = (const float*)d_in[2];
    const float* b1      = (const float*)d_in[3];
    const float* W1_root = (const float*)d_in[4];
    const float* W2_rel  = (const float*)d_in[5];
    const float* b2      = (const float*)d_in[6];
    const float* W2_root = (const float*)d_in[7];
    float*       out     = (float*)d_out;

    const int M = in_sizes[0] / D;          // 20000
    const int E = in_sizes[1] / 2;          // 640000

    void *tptr = nullptr, *hptr = nullptr;
    cudaGetSymbolAddress(&tptr, g_T);
    cudaGetSymbolAddress(&hptr, g_H);
    float* T = (float*)tptr;
    float* H = (float*)hptr;

    dim3 ggrid((M + 127) / 128, 2);

    detect_dtype<<<1, 256>>>((const unsigned int*)ei);
    // Layer 1: T = x@W1_rel ; H = x@W1_root + b1
    gemm_dual<false><<<ggrid, 256>>>(x, W1_rel, W1_root, b1, T, H, M);
    // H[dst] += T[src]  (now H = pre-activation of layer 1)
    scatter_add<<<4736, 256>>>(T, ei, H, E);
    // Layer 2 (ReLU fused into A-load): T = relu(H)@W2_rel ; out = relu(H)@W2_root + b2
    gemm_dual<true><<<ggrid, 256>>>(H, W2_rel, W2_root, b2, T, out, M);
    // out[dst] += T[src]
    scatter_add<<<4736, 256>>>(T, ei, out, E);
}

// round 4
// speedup vs baseline: 1.1758x; 1.1758x over previous
#include <cuda_runtime.h>
#include <cuda_bf16.h>
#include <cstdint>

#define D 128
#define MAX_NODES 20000

// ---------------- scratch (allocation-free) ----------------
__device__ __align__(16)  float          g_T[MAX_NODES * D];
__device__ __align__(16)  float          g_H[MAX_NODES * D];
// W^T in split bf16: [mat 0..3][hi|lo][n=128][k=128]
__device__ __align__(256) __nv_bfloat16  g_Wimg[4 * 2 * D * D];
__device__ int g_is64;

__device__ __forceinline__ uint32_t smem_u32(const void* p) {
    uint32_t a;
    asm("{ .reg .u64 t; cvta.to.shared.u64 t, %1; cvt.u32.u64 %0, t; }" : "=r"(a) : "l"(p));
    return a;
}
__device__ __forceinline__ uint32_t pack2(__nv_bfloat16 a, __nv_bfloat16 b) {
    __nv_bfloat162 v; v.x = a; v.y = b;
    return *reinterpret_cast<uint32_t*>(&v);
}

// ---------------- SMEM layout (bytes). Rows padded to 136 bf16 (272B). ----
#define PITCH    272
#define SM_BIAS  0
#define SM_AHI   512
#define SM_ALO   (512 + 34816)
#define SM_WHI   (512 + 2 * 34816)
#define SM_WLO   (512 + 3 * 34816)
#define SM_TOTAL (512 + 4 * 34816)

// ----------------------------------------------------------------------------
// detect edge_index dtype (int64 vs int32)
// ----------------------------------------------------------------------------
__global__ void detect_dtype(const unsigned int* __restrict__ w)
{
    __shared__ int any;
    if (threadIdx.x == 0) any = 0;
    __syncthreads();
    int found = 0;
    for (int i = threadIdx.x; i < 2048; i += blockDim.x)
        if (w[2 * i + 1] != 0u) found = 1;
    if (found) atomicOr(&any, 1);
    __syncthreads();
    if (threadIdx.x == 0) g_is64 = any ? 0 : 1;
}

// ----------------------------------------------------------------------------
// Weight prep: W -> W^T split bf16 (hi/lo) row-major [n][k].
// grid (4 mats, 8 k-chunks), 128 threads = n.
// ----------------------------------------------------------------------------
__global__ __launch_bounds__(128) void wprep(const float* W0, const float* W1,
                                             const float* W2, const float* W3)
{
    const float* Ws[4] = {W0, W1, W2, W3};
    const float* W = Ws[blockIdx.x];
    __nv_bfloat16* hiimg = g_Wimg + (size_t)blockIdx.x * 2 * D * D;
    __nv_bfloat16* loimg = hiimg + D * D;
    const int n = threadIdx.x;
    const int k0 = blockIdx.y * 16;

    for (int k = k0; k < k0 + 16; k += 2) {
        float a = W[(size_t)k * D + n];
        float b = W[(size_t)(k + 1) * D + n];
        __nv_bfloat16 ha = __float2bfloat16_rn(a), hb = __float2bfloat16_rn(b);
        float la = a - __bfloat162float(ha);
        float lb = b - __bfloat162float(hb);
        *(uint32_t*)(hiimg + (size_t)n * D + k) = pack2(ha, hb);
        *(uint32_t*)(loimg + (size_t)n * D + k) = pack2(__float2bfloat16_rn(la),
                                                        __float2bfloat16_rn(lb));
    }
}

// ----------------------------------------------------------------------------
// mma.sync dual GEMM: C_y = act(A) @ W_y (+bias), y = blockIdx.y.
// Split-bf16 3-pass into fp32 accumulators.
// 256 threads (8 warps, 2m x 4n), warp tile 64x32, CTA tile 128x128, K=128.
// ----------------------------------------------------------------------------
template <bool RELU>
__global__ __launch_bounds__(256, 1) void gemm_mma(
    const float* __restrict__ A,
    const __nv_bfloat16* __restrict__ Wimg,  // layer base: [rel(hi|lo) | root(hi|lo)]
    const float* __restrict__ bias,
    float* __restrict__ Trel,
    float* __restrict__ Hout,
    int M)
{
    extern __shared__ char smem[];
    const uint32_t sb = smem_u32(smem);
    const int tid = threadIdx.x, wid = tid >> 5, lane = tid & 31;
    const int sel = blockIdx.y;
    const int m0 = blockIdx.x * 128;
    float* __restrict__ C = sel ? Hout : Trel;

    // bias (zeros for rel path)
    if (tid < 128) ((float*)(smem + SM_BIAS))[tid] = sel ? bias[tid] : 0.0f;

    // ---- copy W image (hi then lo), pad rows to PITCH ----
    {
        const uint4* src = reinterpret_cast<const uint4*>(Wimg + (size_t)sel * (2 * D * D));
#pragma unroll
        for (int i = 0; i < 16; i++) {
            int idx = tid + i * 256;             // 0..4095 uint4
            int half = idx >> 11;                // 0: hi, 1: lo
            int r = (idx & 2047) >> 4;           // n row
            int w = idx & 15;                    // uint4 within row
            uint4 v = src[idx];
            *reinterpret_cast<uint4*>(smem + (half ? SM_WLO : SM_WHI) + r * PITCH + w * 16) = v;
        }
    }

    // ---- load + split A tile: thread t -> row t/2, 64-col half t&1 ----
    {
        const int r = tid >> 1;
        const int ch = (tid & 1) * 64;
        const int gr = m0 + r;
        const float4* arow = (gr < M) ? reinterpret_cast<const float4*>(A + (size_t)gr * D + ch)
                                      : nullptr;
#pragma unroll
        for (int j = 0; j < 8; j++) {            // 8 floats per iter
            float v[8];
            if (arow) {
                float4 a = arow[j * 2], b = arow[j * 2 + 1];
                v[0] = a.x; v[1] = a.y; v[2] = a.z; v[3] = a.w;
                v[4] = b.x; v[5] = b.y; v[6] = b.z; v[7] = b.w;
                if (RELU) {
#pragma unroll
                    for (int q = 0; q < 8; q++) v[q] = fmaxf(v[q], 0.0f);
                }
            } else {
#pragma unroll
                for (int q = 0; q < 8; q++) v[q] = 0.0f;
            }
            uint32_t hi[4], lo[4];
#pragma unroll
            for (int p = 0; p < 4; p++) {
                float a = v[2 * p], b = v[2 * p + 1];
                __nv_bfloat16 ha = __float2bfloat16_rn(a), hb = __float2bfloat16_rn(b);
                float la = a - __bfloat162float(ha);
                float lb = b - __bfloat162float(hb);
                hi[p] = pack2(ha, hb);
                lo[p] = pack2(__float2bfloat16_rn(la), __float2bfloat16_rn(lb));
            }
            uint32_t off = r * PITCH + (ch + j * 8) * 2;
            *reinterpret_cast<uint4*>(smem + SM_AHI + off) = make_uint4(hi[0], hi[1], hi[2], hi[3]);
            *reinterpret_cast<uint4*>(smem + SM_ALO + off) = make_uint4(lo[0], lo[1], lo[2], lo[3]);
        }
    }
    __syncthreads();

    // ---- compute ----
    const int wm = (wid >> 2) * 64;              // warp m offset
    const int wn = (wid & 3) * 32;               // warp n offset
    float c[4][4][4];
#pragma unroll
    for (int mt = 0; mt < 4; mt++)
#pragma unroll
        for (int nt = 0; nt < 4; nt++)
#pragma unroll
            for (int q = 0; q < 4; q++) c[mt][nt][q] = 0.0f;

#pragma unroll
    for (int pass = 0; pass < 3; pass++) {
        const uint32_t Ab = sb + ((pass == 1) ? SM_ALO : SM_AHI);
        const uint32_t Wb = sb + ((pass == 2) ? SM_WLO : SM_WHI);
#pragma unroll
        for (int ks = 0; ks < 8; ks++) {
            const int k0 = ks * 16;
            // B fragments (4 n-tiles): non-trans ldmatrix.x2 on row-major W^T
            uint32_t bfr[4][2];
#pragma unroll
            for (int nt = 0; nt < 4; nt++) {
                uint32_t addr = Wb + (wn + nt * 8 + (lane & 7)) * PITCH
                              + (k0 + ((lane >> 3) & 1) * 8) * 2;
                asm volatile("ldmatrix.sync.aligned.m8n8.x2.shared.b16 {%0,%1}, [%2];"
                             : "=r"(bfr[nt][0]), "=r"(bfr[nt][1]) : "r"(addr));
            }
            // A fragments (4 m-tiles): ldmatrix.x4
            uint32_t afr[4][4];
#pragma unroll
            for (int mt = 0; mt < 4; mt++) {
                uint32_t addr = Ab + (wm + mt * 16 + (lane & 15)) * PITCH
                              + (k0 + (lane >> 4) * 8) * 2;
                asm volatile("ldmatrix.sync.aligned.m8n8.x4.shared.b16 {%0,%1,%2,%3}, [%4];"
                             : "=r"(afr[mt][0]), "=r"(afr[mt][1]),
                               "=r"(afr[mt][2]), "=r"(afr[mt][3]) : "r"(addr));
            }
#pragma unroll
            for (int mt = 0; mt < 4; mt++)
#pragma unroll
                for (int nt = 0; nt < 4; nt++)
                    asm volatile(
                        "mma.sync.aligned.m16n8k16.row.col.f32.bf16.bf16.f32 "
                        "{%0,%1,%2,%3}, {%4,%5,%6,%7}, {%8,%9}, {%0,%1,%2,%3};"
                        : "+f"(c[mt][nt][0]), "+f"(c[mt][nt][1]),
                          "+f"(c[mt][nt][2]), "+f"(c[mt][nt][3])
                        : "r"(afr[mt][0]), "r"(afr[mt][1]), "r"(afr[mt][2]), "r"(afr[mt][3]),
                          "r"(bfr[nt][0]), "r"(bfr[nt][1]));
        }
    }

    // ---- epilogue: +bias, store float2 pairs ----
    const float* sbias = (const float*)(smem + SM_BIAS);
    const int g = lane >> 2;
    const int q4 = lane & 3;
#pragma unroll
    for (int mt = 0; mt < 4; mt++) {
        const int r0 = m0 + wm + mt * 16 + g;
#pragma unroll
        for (int nt = 0; nt < 4; nt++) {
            const int col = wn + nt * 8 + 2 * q4;
            const float b0 = sbias[col], b1 = sbias[col + 1];
            if (r0 < M) {
                float2 v = make_float2(c[mt][nt][0] + b0, c[mt][nt][1] + b1);
                *reinterpret_cast<float2*>(C + (size_t)r0 * D + col) = v;
            }
            if (r0 + 8 < M) {
                float2 v = make_float2(c[mt][nt][2] + b0, c[mt][nt][3] + b1);
                *reinterpret_cast<float2*>(C + (size_t)(r0 + 8) * D + col) = v;
            }
        }
    }
}

// ----------------------------------------------------------------------------
// Edge scatter: H[dst] += T[src], warp per edge, lane owns a float4 chunk.
// ----------------------------------------------------------------------------
__global__ __launch_bounds__(256) void scatter_add(
    const float* __restrict__ T,
    const void* __restrict__ ei_raw,
    float* __restrict__ H,
    int E)
{
    const int warp  = (blockIdx.x * blockDim.x + threadIdx.x) >> 5;
    const int nwarp = (gridDim.x * blockDim.x) >> 5;
    const int off   = (threadIdx.x & 31) * 4;
    const int is64  = g_is64;
    const int*       ei32 = (const int*)ei_raw;
    const long long* ei64 = (const long long*)ei_raw;

    for (int e = warp; e < E; e += nwarp) {
        int src, dst;
        if (is64) { src = (int)ei64[e]; dst = (int)ei64[E + e]; }
        else      { src = ei32[e];      dst = ei32[E + e]; }
        const float4 v = *reinterpret_cast<const float4*>(T + (size_t)src * D + off);
        float* p = H + (size_t)dst * D + off;
        asm volatile("red.global.add.v4.f32 [%0], {%1, %2, %3, %4};"
                     :: "l"(p), "f"(v.x), "f"(v.y), "f"(v.z), "f"(v.w)
                     : "memory");
    }
}

// ----------------------------------------------------------------------------
// kernel_launch
// Inputs: x, edge_index, W1_rel, b1_rel, W1_root, W2_rel, b2_rel, W2_root
// ----------------------------------------------------------------------------
extern "C" void kernel_launch(void* const* d_in, const int* in_sizes, int n_in,
                              void* d_out, int out_size)
{
    const float* x       = (const float*)d_in[0];
    const void*  ei      = d_in[1];
    const float* W1_rel  = (const float*)d_in[2];
    const float* b1      = (const float*)d_in[3];
    const float* W1_root = (const float*)d_in[4];
    const float* W2_rel  = (const float*)d_in[5];
    const float* b2      = (const float*)d_in[6];
    const float* W2_root = (const float*)d_in[7];
    float*       out     = (float*)d_out;

    const int M = in_sizes[0] / D;   // 20000
    const int E = in_sizes[1] / 2;   // 640000

    void *tptr = nullptr, *hptr = nullptr, *wptr = nullptr;
    cudaGetSymbolAddress(&tptr, g_T);
    cudaGetSymbolAddress(&hptr, g_H);
    cudaGetSymbolAddress(&wptr, g_Wimg);
    float* T = (float*)tptr;
    float* H = (float*)hptr;
    const __nv_bfloat16* Wimg = (const __nv_bfloat16*)wptr;

    cudaFuncSetAttribute(gemm_mma<false>, cudaFuncAttributeMaxDynamicSharedMemorySize, SM_TOTAL);
    cudaFuncSetAttribute(gemm_mma<true>,  cudaFuncAttributeMaxDynamicSharedMemorySize, SM_TOTAL);

    dim3 ggrid((M + 127) / 128, 2);

    detect_dtype<<<1, 256>>>((const unsigned int*)ei);
    wprep<<<dim3(4, 8), 128>>>(W1_rel, W1_root, W2_rel, W2_root);

    // Layer 1: T = x@W1_rel ; H = x@W1_root + b1
    gemm_mma<false><<<ggrid, 256, SM_TOTAL>>>(x, Wimg, b1, T, H, M);
    scatter_add<<<4736, 256>>>(T, ei, H, E);
    // Layer 2 (ReLU fused into A conversion)
    gemm_mma<true><<<ggrid, 256, SM_TOTAL>>>(H, Wimg + 2 * (2 * D * D), b2, T, out, M);
    scatter_add<<<4736, 256>>>(T, ei, out, E);
}

// round 5
// speedup vs baseline: 1.3935x; 1.1851x over previous
#include <cuda_runtime.h>
#include <cuda_bf16.h>
#include <cstdint>

#define D 128
#define MAX_NODES 20000
#define MAX_EDGES 640000

// ---------------- scratch (allocation-free) ----------------
__device__ __align__(16)  float          g_T[MAX_NODES * D];
__device__ __align__(16)  float          g_H[MAX_NODES * D];
__device__ __align__(256) __nv_bfloat16  g_Wimg[4 * 2 * D * D];
__device__ int g_is64;
__device__ int g_cnt[MAX_NODES];          // histogram / fill cursor
__device__ int g_rowptr[MAX_NODES + 1];
__device__ int g_col[MAX_EDGES];          // src indices grouped by dst

__device__ __forceinline__ uint32_t smem_u32(const void* p) {
    uint32_t a;
    asm("{ .reg .u64 t; cvta.to.shared.u64 t, %1; cvt.u32.u64 %0, t; }" : "=r"(a) : "l"(p));
    return a;
}
__device__ __forceinline__ uint32_t pack2(__nv_bfloat16 a, __nv_bfloat16 b) {
    __nv_bfloat162 v; v.x = a; v.y = b;
    return *reinterpret_cast<uint32_t*>(&v);
}

// ---------------- SMEM layout (bytes). Rows padded to 136 bf16 (272B). ----
#define PITCH    272
#define SM_BIAS  0
#define SM_AHI   512
#define SM_ALO   (512 + 34816)
#define SM_WHI   (512 + 2 * 34816)
#define SM_WLO   (512 + 3 * 34816)
#define SM_TOTAL (512 + 4 * 34816)

// ----------------------------------------------------------------------------
// detect edge_index dtype (int64 vs int32)
// ----------------------------------------------------------------------------
__global__ void detect_dtype(const unsigned int* __restrict__ w)
{
    __shared__ int any;
    if (threadIdx.x == 0) any = 0;
    __syncthreads();
    int found = 0;
    for (int i = threadIdx.x; i < 2048; i += blockDim.x)
        if (w[2 * i + 1] != 0u) found = 1;
    if (found) atomicOr(&any, 1);
    __syncthreads();
    if (threadIdx.x == 0) g_is64 = any ? 0 : 1;
}

// ---------------- CSR build ----------------
__global__ void zero_cnt(int N)
{
    int i = blockIdx.x * blockDim.x + threadIdx.x;
    if (i < N) g_cnt[i] = 0;
}

__global__ void hist_dst(const void* __restrict__ ei_raw, int E)
{
    const int is64 = g_is64;
    const int*       ei32 = (const int*)ei_raw;
    const long long* ei64 = (const long long*)ei_raw;
    int e = blockIdx.x * blockDim.x + threadIdx.x;
    if (e < E) {
        int dst = is64 ? (int)ei64[E + e] : ei32[E + e];
        atomicAdd(&g_cnt[dst], 1);
    }
}

// single-block exclusive scan over g_cnt -> g_rowptr; zeroes g_cnt for reuse
__global__ __launch_bounds__(1024) void scan_rowptr(int N, int E)
{
    __shared__ int sums[1024];
    const int t = threadIdx.x;
    const int CH = 20;                       // 1024*20 >= 20000
    const int base = t * CH;
    int vals[CH];
    int s = 0;
#pragma unroll
    for (int i = 0; i < CH; i++) {
        int r = base + i;
        vals[i] = (r < N) ? g_cnt[r] : 0;
        s += vals[i];
    }
    sums[t] = s;
    __syncthreads();
    for (int off = 1; off < 1024; off <<= 1) {
        int v = (t >= off) ? sums[t - off] : 0;
        __syncthreads();
        sums[t] += v;
        __syncthreads();
    }
    int pre = (t == 0) ? 0 : sums[t - 1];
#pragma unroll
    for (int i = 0; i < CH; i++) {
        int r = base + i;
        if (r < N) { g_rowptr[r] = pre; pre += vals[i]; g_cnt[r] = 0; }
    }
    if (t == 0) g_rowptr[N] = E;
}

__global__ void fill_col(const void* __restrict__ ei_raw, int E)
{
    const int is64 = g_is64;
    const int*       ei32 = (const int*)ei_raw;
    const long long* ei64 = (const long long*)ei_raw;
    int e = blockIdx.x * blockDim.x + threadIdx.x;
    if (e < E) {
        int src, dst;
        if (is64) { src = (int)ei64[e]; dst = (int)ei64[E + e]; }
        else      { src = ei32[e];      dst = ei32[E + e]; }
        int pos = atomicAdd(&g_cnt[dst], 1);
        g_col[g_rowptr[dst] + pos] = src;
    }
}

// ----------------------------------------------------------------------------
// Weight prep: W -> W^T split bf16 (hi/lo) row-major [n][k].
// ----------------------------------------------------------------------------
__global__ __launch_bounds__(128) void wprep(const float* W0, const float* W1,
                                             const float* W2, const float* W3)
{
    const float* Ws[4] = {W0, W1, W2, W3};
    const float* W = Ws[blockIdx.x];
    __nv_bfloat16* hiimg = g_Wimg + (size_t)blockIdx.x * 2 * D * D;
    __nv_bfloat16* loimg = hiimg + D * D;
    const int n = threadIdx.x;
    const int k0 = blockIdx.y * 16;

    for (int k = k0; k < k0 + 16; k += 2) {
        float a = W[(size_t)k * D + n];
        float b = W[(size_t)(k + 1) * D + n];
        __nv_bfloat16 ha = __float2bfloat16_rn(a), hb = __float2bfloat16_rn(b);
        float la = a - __bfloat162float(ha);
        float lb = b - __bfloat162float(hb);
        *(uint32_t*)(hiimg + (size_t)n * D + k) = pack2(ha, hb);
        *(uint32_t*)(loimg + (size_t)n * D + k) = pack2(__float2bfloat16_rn(la),
                                                        __float2bfloat16_rn(lb));
    }
}

// ----------------------------------------------------------------------------
// mma.sync dual GEMM: C_y = act(A) @ W_y (+bias), y = blockIdx.y.
// Split-bf16 3-pass into fp32 accumulators.
// ----------------------------------------------------------------------------
template <bool RELU>
__global__ __launch_bounds__(256, 1) void gemm_mma(
    const float* __restrict__ A,
    const __nv_bfloat16* __restrict__ Wimg,
    const float* __restrict__ bias,
    float* __restrict__ Trel,
    float* __restrict__ Hout,
    int M)
{
    extern __shared__ char smem[];
    const uint32_t sb = smem_u32(smem);
    const int tid = threadIdx.x, wid = tid >> 5, lane = tid & 31;
    const int sel = blockIdx.y;
    const int m0 = blockIdx.x * 128;
    float* __restrict__ C = sel ? Hout : Trel;

    if (tid < 128) ((float*)(smem + SM_BIAS))[tid] = sel ? bias[tid] : 0.0f;

    // ---- copy W image ----
    {
        const uint4* src = reinterpret_cast<const uint4*>(Wimg + (size_t)sel * (2 * D * D));
#pragma unroll
        for (int i = 0; i < 16; i++) {
            int idx = tid + i * 256;
            int half = idx >> 11;
            int r = (idx & 2047) >> 4;
            int w = idx & 15;
            uint4 v = src[idx];
            *reinterpret_cast<uint4*>(smem + (half ? SM_WLO : SM_WHI) + r * PITCH + w * 16) = v;
        }
    }

    // ---- load + split A tile ----
    {
        const int r = tid >> 1;
        const int ch = (tid & 1) * 64;
        const int gr = m0 + r;
        const float4* arow = (gr < M) ? reinterpret_cast<const float4*>(A + (size_t)gr * D + ch)
                                      : nullptr;
#pragma unroll
        for (int j = 0; j < 8; j++) {
            float v[8];
            if (arow) {
                float4 a = arow[j * 2], b = arow[j * 2 + 1];
                v[0] = a.x; v[1] = a.y; v[2] = a.z; v[3] = a.w;
                v[4] = b.x; v[5] = b.y; v[6] = b.z; v[7] = b.w;
                if (RELU) {
#pragma unroll
                    for (int q = 0; q < 8; q++) v[q] = fmaxf(v[q], 0.0f);
                }
            } else {
#pragma unroll
                for (int q = 0; q < 8; q++) v[q] = 0.0f;
            }
            uint32_t hi[4], lo[4];
#pragma unroll
            for (int p = 0; p < 4; p++) {
                float a = v[2 * p], b = v[2 * p + 1];
                __nv_bfloat16 ha = __float2bfloat16_rn(a), hb = __float2bfloat16_rn(b);
                float la = a - __bfloat162float(ha);
                float lb = b - __bfloat162float(hb);
                hi[p] = pack2(ha, hb);
                lo[p] = pack2(__float2bfloat16_rn(la), __float2bfloat16_rn(lb));
            }
            uint32_t off = r * PITCH + (ch + j * 8) * 2;
            *reinterpret_cast<uint4*>(smem + SM_AHI + off) = make_uint4(hi[0], hi[1], hi[2], hi[3]);
            *reinterpret_cast<uint4*>(smem + SM_ALO + off) = make_uint4(lo[0], lo[1], lo[2], lo[3]);
        }
    }
    __syncthreads();

    // ---- compute ----
    const int wm = (wid >> 2) * 64;
    const int wn = (wid & 3) * 32;
    float c[4][4][4];
#pragma unroll
    for (int mt = 0; mt < 4; mt++)
#pragma unroll
        for (int nt = 0; nt < 4; nt++)
#pragma unroll
            for (int q = 0; q < 4; q++) c[mt][nt][q] = 0.0f;

#pragma unroll
    for (int pass = 0; pass < 3; pass++) {
        const uint32_t Ab = sb + ((pass == 1) ? SM_ALO : SM_AHI);
        const uint32_t Wb = sb + ((pass == 2) ? SM_WLO : SM_WHI);
#pragma unroll
        for (int ks = 0; ks < 8; ks++) {
            const int k0 = ks * 16;
            uint32_t bfr[4][2];
#pragma unroll
            for (int nt = 0; nt < 4; nt++) {
                uint32_t addr = Wb + (wn + nt * 8 + (lane & 7)) * PITCH
                              + (k0 + ((lane >> 3) & 1) * 8) * 2;
                asm volatile("ldmatrix.sync.aligned.m8n8.x2.shared.b16 {%0,%1}, [%2];"
                             : "=r"(bfr[nt][0]), "=r"(bfr[nt][1]) : "r"(addr));
            }
            uint32_t afr[4][4];
#pragma unroll
            for (int mt = 0; mt < 4; mt++) {
                uint32_t addr = Ab + (wm + mt * 16 + (lane & 15)) * PITCH
                              + (k0 + (lane >> 4) * 8) * 2;
                asm volatile("ldmatrix.sync.aligned.m8n8.x4.shared.b16 {%0,%1,%2,%3}, [%4];"
                             : "=r"(afr[mt][0]), "=r"(afr[mt][1]),
                               "=r"(afr[mt][2]), "=r"(afr[mt][3]) : "r"(addr));
            }
#pragma unroll
            for (int mt = 0; mt < 4; mt++)
#pragma unroll
                for (int nt = 0; nt < 4; nt++)
                    asm volatile(
                        "mma.sync.aligned.m16n8k16.row.col.f32.bf16.bf16.f32 "
                        "{%0,%1,%2,%3}, {%4,%5,%6,%7}, {%8,%9}, {%0,%1,%2,%3};"
                        : "+f"(c[mt][nt][0]), "+f"(c[mt][nt][1]),
                          "+f"(c[mt][nt][2]), "+f"(c[mt][nt][3])
                        : "r"(afr[mt][0]), "r"(afr[mt][1]), "r"(afr[mt][2]), "r"(afr[mt][3]),
                          "r"(bfr[nt][0]), "r"(bfr[nt][1]));
        }
    }

    // ---- epilogue ----
    const float* sbias = (const float*)(smem + SM_BIAS);
    const int g = lane >> 2;
    const int q4 = lane & 3;
#pragma unroll
    for (int mt = 0; mt < 4; mt++) {
        const int r0 = m0 + wm + mt * 16 + g;
#pragma unroll
        for (int nt = 0; nt < 4; nt++) {
            const int col = wn + nt * 8 + 2 * q4;
            const float b0 = sbias[col], b1 = sbias[col + 1];
            if (r0 < M) {
                float2 v = make_float2(c[mt][nt][0] + b0, c[mt][nt][1] + b1);
                *reinterpret_cast<float2*>(C + (size_t)r0 * D + col) = v;
            }
            if (r0 + 8 < M) {
                float2 v = make_float2(c[mt][nt][2] + b0, c[mt][nt][3] + b1);
                *reinterpret_cast<float2*>(C + (size_t)(r0 + 8) * D + col) = v;
            }
        }
    }
}

// ----------------------------------------------------------------------------
// CSR gather: H[d] += sum_{j in adj(d)} T[col[j]]. Warp per dst node, lane
// owns a float4 chunk. Register accumulation, single RMW of H per row.
// ----------------------------------------------------------------------------
__global__ __launch_bounds__(256) void gather_add(
    const float* __restrict__ T,
    float* __restrict__ H,
    int N)
{
    const int warp  = (blockIdx.x * blockDim.x + threadIdx.x) >> 5;
    const int nwarp = (gridDim.x * blockDim.x) >> 5;
    const int off   = (threadIdx.x & 31) * 4;

    for (int d = warp; d < N; d += nwarp) {
        const int beg = g_rowptr[d];
        const int end = g_rowptr[d + 1];
        float4 acc = *reinterpret_cast<const float4*>(H + (size_t)d * D + off);
        int j = beg;
        for (; j + 4 <= end; j += 4) {
            const int s0 = g_col[j], s1 = g_col[j + 1];
            const int s2 = g_col[j + 2], s3 = g_col[j + 3];
            const float4 v0 = *reinterpret_cast<const float4*>(T + (size_t)s0 * D + off);
            const float4 v1 = *reinterpret_cast<const float4*>(T + (size_t)s1 * D + off);
            const float4 v2 = *reinterpret_cast<const float4*>(T + (size_t)s2 * D + off);
            const float4 v3 = *reinterpret_cast<const float4*>(T + (size_t)s3 * D + off);
            acc.x += v0.x; acc.y += v0.y; acc.z += v0.z; acc.w += v0.w;
            acc.x += v1.x; acc.y += v1.y; acc.z += v1.z; acc.w += v1.w;
            acc.x += v2.x; acc.y += v2.y; acc.z += v2.z; acc.w += v2.w;
            acc.x += v3.x; acc.y += v3.y; acc.z += v3.z; acc.w += v3.w;
        }
        for (; j < end; j++) {
            const int s = g_col[j];
            const float4 v = *reinterpret_cast<const float4*>(T + (size_t)s * D + off);
            acc.x += v.x; acc.y += v.y; acc.z += v.z; acc.w += v.w;
        }
        *reinterpret_cast<float4*>(H + (size_t)d * D + off) = acc;
    }
}

// ----------------------------------------------------------------------------
// kernel_launch
// Inputs: x, edge_index, W1_rel, b1_rel, W1_root, W2_rel, b2_rel, W2_root
// ----------------------------------------------------------------------------
extern "C" void kernel_launch(void* const* d_in, const int* in_sizes, int n_in,
                              void* d_out, int out_size)
{
    const float* x       = (const float*)d_in[0];
    const void*  ei      = d_in[1];
    const float* W1_rel  = (const float*)d_in[2];
    const float* b1      = (const float*)d_in[3];
    const float* W1_root = (const float*)d_in[4];
    const float* W2_rel  = (const float*)d_in[5];
    const float* b2      = (const float*)d_in[6];
    const float* W2_root = (const float*)d_in[7];
    float*       out     = (float*)d_out;

    const int M = in_sizes[0] / D;   // 20000
    const int E = in_sizes[1] / 2;   // 640000

    void *tptr = nullptr, *hptr = nullptr, *wptr = nullptr;
    cudaGetSymbolAddress(&tptr, g_T);
    cudaGetSymbolAddress(&hptr, g_H);
    cudaGetSymbolAddress(&wptr, g_Wimg);
    float* T = (float*)tptr;
    float* H = (float*)hptr;
    const __nv_bfloat16* Wimg = (const __nv_bfloat16*)wptr;

    cudaFuncSetAttribute(gemm_mma<false>, cudaFuncAttributeMaxDynamicSharedMemorySize, SM_TOTAL);
    cudaFuncSetAttribute(gemm_mma<true>,  cudaFuncAttributeMaxDynamicSharedMemorySize, SM_TOTAL);

    dim3 ggrid((M + 127) / 128, 2);
    const int eblocks = (E + 255) / 256;
    const int nblocks = (M + 255) / 256;

    detect_dtype<<<1, 256>>>((const unsigned int*)ei);
    // CSR build (dst-sorted adjacency)
    zero_cnt<<<nblocks, 256>>>(M);
    hist_dst<<<eblocks, 256>>>(ei, E);
    scan_rowptr<<<1, 1024>>>(M, E);
    fill_col<<<eblocks, 256>>>(ei, E);
    // weights
    wprep<<<dim3(4, 8), 128>>>(W1_rel, W1_root, W2_rel, W2_root);

    // Layer 1: T = x@W1_rel ; H = x@W1_root + b1 ; H += gather(T)
    gemm_mma<false><<<ggrid, 256, SM_TOTAL>>>(x, Wimg, b1, T, H, M);
    gather_add<<<2500, 256>>>(T, H, M);
    // Layer 2 (ReLU fused into A conversion)
    gemm_mma<true><<<ggrid, 256, SM_TOTAL>>>(H, Wimg + 2 * (2 * D * D), b2, T, out, M);
    gather_add<<<2500, 256>>>(T, out, M);
}

// round 6
// speedup vs baseline: 1.6097x; 1.1551x over previous
#include <cuda_runtime.h>
#include <cuda_bf16.h>
#include <cstdint>

#define D 128
#define MAX_NODES 20000
#define MAX_EDGES 640000
#define SCAN_B 512

// ---------------- scratch (allocation-free) ----------------
__device__ __align__(16)  float          g_T[MAX_NODES * D];
__device__ __align__(16)  float          g_H[MAX_NODES * D];
__device__ __align__(256) __nv_bfloat16  g_Wimg[4 * 2 * D * D];
__device__ int g_is64;
__device__ int g_cnt[MAX_NODES];          // histogram / fill cursor
__device__ int g_rowptr[MAX_NODES + 1];
__device__ int g_col[MAX_EDGES];          // src indices grouped by dst
__device__ int g_bsum[64];                // per-block sums for the scan

__device__ __forceinline__ uint32_t smem_u32(const void* p) {
    uint32_t a;
    asm("{ .reg .u64 t; cvta.to.shared.u64 t, %1; cvt.u32.u64 %0, t; }" : "=r"(a) : "l"(p));
    return a;
}
__device__ __forceinline__ uint32_t pack2(__nv_bfloat16 a, __nv_bfloat16 b) {
    __nv_bfloat162 v; v.x = a; v.y = b;
    return *reinterpret_cast<uint32_t*>(&v);
}

// ---------------- SMEM layout (bytes). Rows padded to 136 bf16 (272B). ----
#define PITCH    272
#define SM_BIAS  0
#define SM_AHI   512
#define SM_ALO   (512 + 34816)
#define SM_WHI   (512 + 2 * 34816)
#define SM_WLO   (512 + 3 * 34816)
#define SM_TOTAL (512 + 4 * 34816)

// ----------------------------------------------------------------------------
// init: zero g_cnt across the grid; block 0 additionally detects index dtype.
// ----------------------------------------------------------------------------
__global__ void init_detect(const unsigned int* __restrict__ w, int N)
{
    int i = blockIdx.x * blockDim.x + threadIdx.x;
    if (i < N) g_cnt[i] = 0;
    if (blockIdx.x == 0) {
        __shared__ int any;
        if (threadIdx.x == 0) any = 0;
        __syncthreads();
        int found = 0;
        for (int k = threadIdx.x; k < 2048; k += blockDim.x)
            if (w[2 * k + 1] != 0u) found = 1;
        if (found) atomicOr(&any, 1);
        __syncthreads();
        if (threadIdx.x == 0) g_is64 = any ? 0 : 1;
    }
}

__global__ void hist_dst(const void* __restrict__ ei_raw, int E)
{
    const int is64 = g_is64;
    const int*       ei32 = (const int*)ei_raw;
    const long long* ei64 = (const long long*)ei_raw;
    int e = blockIdx.x * blockDim.x + threadIdx.x;
    if (e < E) {
        int dst = is64 ? (int)ei64[E + e] : ei32[E + e];
        atomicAdd(&g_cnt[dst], 1);
    }
}

// ---- 3-phase scan: reduce -> top scan -> write (+zero cnt) ----
__global__ __launch_bounds__(SCAN_B) void scan_reduce(int N)
{
    const int tid = threadIdx.x, lane = tid & 31, wid = tid >> 5;
    int i = blockIdx.x * SCAN_B + tid;
    int v = (i < N) ? g_cnt[i] : 0;
#pragma unroll
    for (int o = 16; o > 0; o >>= 1) v += __shfl_down_sync(0xFFFFFFFFu, v, o);
    __shared__ int ws[SCAN_B / 32];
    if (lane == 0) ws[wid] = v;
    __syncthreads();
    if (wid == 0) {
        int s = (lane < SCAN_B / 32) ? ws[lane] : 0;
#pragma unroll
        for (int o = 8; o > 0; o >>= 1) s += __shfl_down_sync(0xFFFFFFFFu, s, o);
        if (lane == 0) g_bsum[blockIdx.x] = s;
    }
}

__global__ void scan_top(int NB, int N, int E)   // 1 warp; NB <= 64
{
    const int l = threadIdx.x;            // 0..31
    int a = (2 * l < NB)     ? g_bsum[2 * l]     : 0;
    int b = (2 * l + 1 < NB) ? g_bsum[2 * l + 1] : 0;
    int s = a + b;
    int incl = s;
#pragma unroll
    for (int o = 1; o < 32; o <<= 1) {
        int t = __shfl_up_sync(0xFFFFFFFFu, incl, o);
        if (l >= o) incl += t;
    }
    int excl = incl - s;
    if (2 * l < NB)     g_bsum[2 * l]     = excl;
    if (2 * l + 1 < NB) g_bsum[2 * l + 1] = excl + a;
    if (l == 0) g_rowptr[N] = E;
}

__global__ __launch_bounds__(SCAN_B) void scan_write(int N)
{
    const int tid = threadIdx.x, lane = tid & 31, wid = tid >> 5;
    int i = blockIdx.x * SCAN_B + tid;
    int v = (i < N) ? g_cnt[i] : 0;
    int incl = v;
#pragma unroll
    for (int o = 1; o < 32; o <<= 1) {
        int t = __shfl_up_sync(0xFFFFFFFFu, incl, o);
        if (lane >= o) incl += t;
    }
    __shared__ int ws[SCAN_B / 32];
    if (lane == 31) ws[wid] = incl;
    __syncthreads();
    if (wid == 0) {
        int s = (lane < SCAN_B / 32) ? ws[lane] : 0;
#pragma unroll
        for (int o = 1; o < 32; o <<= 1) {
            int t = __shfl_up_sync(0xFFFFFFFFu, s, o);
            if (lane >= o) s += t;
        }
        if (lane < SCAN_B / 32) ws[lane] = s;
    }
    __syncthreads();
    int base = g_bsum[blockIdx.x] + (wid ? ws[wid - 1] : 0);
    if (i < N) {
        g_rowptr[i] = base + incl - v;   // exclusive
        g_cnt[i] = 0;                    // reset cursor for fill_col
    }
}

__global__ void fill_col(const void* __restrict__ ei_raw, int E)
{
    const int is64 = g_is64;
    const int*       ei32 = (const int*)ei_raw;
    const long long* ei64 = (const long long*)ei_raw;
    int e = blockIdx.x * blockDim.x + threadIdx.x;
    if (e < E) {
        int src, dst;
        if (is64) { src = (int)ei64[e]; dst = (int)ei64[E + e]; }
        else      { src = ei32[e];      dst = ei32[E + e]; }
        int pos = atomicAdd(&g_cnt[dst], 1);
        g_col[g_rowptr[dst] + pos] = src;
    }
}

// ----------------------------------------------------------------------------
// Weight prep: W -> W^T split bf16 (hi/lo) row-major [n][k].
// ----------------------------------------------------------------------------
__global__ __launch_bounds__(128) void wprep(const float* W0, const float* W1,
                                             const float* W2, const float* W3)
{
    const float* Ws[4] = {W0, W1, W2, W3};
    const float* W = Ws[blockIdx.x];
    __nv_bfloat16* hiimg = g_Wimg + (size_t)blockIdx.x * 2 * D * D;
    __nv_bfloat16* loimg = hiimg + D * D;
    const int n = threadIdx.x;
    const int k0 = blockIdx.y * 16;

    for (int k = k0; k < k0 + 16; k += 2) {
        float a = W[(size_t)k * D + n];
        float b = W[(size_t)(k + 1) * D + n];
        __nv_bfloat16 ha = __float2bfloat16_rn(a), hb = __float2bfloat16_rn(b);
        float la = a - __bfloat162float(ha);
        float lb = b - __bfloat162float(hb);
        *(uint32_t*)(hiimg + (size_t)n * D + k) = pack2(ha, hb);
        *(uint32_t*)(loimg + (size_t)n * D + k) = pack2(__float2bfloat16_rn(la),
                                                        __float2bfloat16_rn(lb));
    }
}

// ----------------------------------------------------------------------------
// mma.sync dual GEMM: C_y = act(A) @ W_y (+bias), y = blockIdx.y.
// Split-bf16 3-pass into fp32 accumulators.
// ----------------------------------------------------------------------------
template <bool RELU>
__global__ __launch_bounds__(256, 1) void gemm_mma(
    const float* __restrict__ A,
    const __nv_bfloat16* __restrict__ Wimg,
    const float* __restrict__ bias,
    float* __restrict__ Trel,
    float* __restrict__ Hout,
    int M)
{
    extern __shared__ char smem[];
    const uint32_t sb = smem_u32(smem);
    const int tid = threadIdx.x, wid = tid >> 5, lane = tid & 31;
    const int sel = blockIdx.y;
    const int m0 = blockIdx.x * 128;
    float* __restrict__ C = sel ? Hout : Trel;

    if (tid < 128) ((float*)(smem + SM_BIAS))[tid] = sel ? bias[tid] : 0.0f;

    // ---- copy W image ----
    {
        const uint4* src = reinterpret_cast<const uint4*>(Wimg + (size_t)sel * (2 * D * D));
#pragma unroll
        for (int i = 0; i < 16; i++) {
            int idx = tid + i * 256;
            int half = idx >> 11;
            int r = (idx & 2047) >> 4;
            int w = idx & 15;
            uint4 v = src[idx];
            *reinterpret_cast<uint4*>(smem + (half ? SM_WLO : SM_WHI) + r * PITCH + w * 16) = v;
        }
    }

    // ---- load + split A tile ----
    {
        const int r = tid >> 1;
        const int ch = (tid & 1) * 64;
        const int gr = m0 + r;
        const float4* arow = (gr < M) ? reinterpret_cast<const float4*>(A + (size_t)gr * D + ch)
                                      : nullptr;
#pragma unroll
        for (int j = 0; j < 8; j++) {
            float v[8];
            if (arow) {
                float4 a = arow[j * 2], b = arow[j * 2 + 1];
                v[0] = a.x; v[1] = a.y; v[2] = a.z; v[3] = a.w;
                v[4] = b.x; v[5] = b.y; v[6] = b.z; v[7] = b.w;
                if (RELU) {
#pragma unroll
                    for (int q = 0; q < 8; q++) v[q] = fmaxf(v[q], 0.0f);
                }
            } else {
#pragma unroll
                for (int q = 0; q < 8; q++) v[q] = 0.0f;
            }
            uint32_t hi[4], lo[4];
#pragma unroll
            for (int p = 0; p < 4; p++) {
                float a = v[2 * p], b = v[2 * p + 1];
                __nv_bfloat16 ha = __float2bfloat16_rn(a), hb = __float2bfloat16_rn(b);
                float la = a - __bfloat162float(ha);
                float lb = b - __bfloat162float(hb);
                hi[p] = pack2(ha, hb);
                lo[p] = pack2(__float2bfloat16_rn(la), __float2bfloat16_rn(lb));
            }
            uint32_t off = r * PITCH + (ch + j * 8) * 2;
            *reinterpret_cast<uint4*>(smem + SM_AHI + off) = make_uint4(hi[0], hi[1], hi[2], hi[3]);
            *reinterpret_cast<uint4*>(smem + SM_ALO + off) = make_uint4(lo[0], lo[1], lo[2], lo[3]);
        }
    }
    __syncthreads();

    // ---- compute ----
    const int wm = (wid >> 2) * 64;
    const int wn = (wid & 3) * 32;
    float c[4][4][4];
#pragma unroll
    for (int mt = 0; mt < 4; mt++)
#pragma unroll
        for (int nt = 0; nt < 4; nt++)
#pragma unroll
            for (int q = 0; q < 4; q++) c[mt][nt][q] = 0.0f;

#pragma unroll
    for (int pass = 0; pass < 3; pass++) {
        const uint32_t Ab = sb + ((pass == 1) ? SM_ALO : SM_AHI);
        const uint32_t Wb = sb + ((pass == 2) ? SM_WLO : SM_WHI);
#pragma unroll
        for (int ks = 0; ks < 8; ks++) {
            const int k0 = ks * 16;
            uint32_t bfr[4][2];
#pragma unroll
            for (int nt = 0; nt < 4; nt++) {
                uint32_t addr = Wb + (wn + nt * 8 + (lane & 7)) * PITCH
                              + (k0 + ((lane >> 3) & 1) * 8) * 2;
                asm volatile("ldmatrix.sync.aligned.m8n8.x2.shared.b16 {%0,%1}, [%2];"
                             : "=r"(bfr[nt][0]), "=r"(bfr[nt][1]) : "r"(addr));
            }
            uint32_t afr[4][4];
#pragma unroll
            for (int mt = 0; mt < 4; mt++) {
                uint32_t addr = Ab + (wm + mt * 16 + (lane & 15)) * PITCH
                              + (k0 + (lane >> 4) * 8) * 2;
                asm volatile("ldmatrix.sync.aligned.m8n8.x4.shared.b16 {%0,%1,%2,%3}, [%4];"
                             : "=r"(afr[mt][0]), "=r"(afr[mt][1]),
                               "=r"(afr[mt][2]), "=r"(afr[mt][3]) : "r"(addr));
            }
#pragma unroll
            for (int mt = 0; mt < 4; mt++)
#pragma unroll
                for (int nt = 0; nt < 4; nt++)
                    asm volatile(
                        "mma.sync.aligned.m16n8k16.row.col.f32.bf16.bf16.f32 "
                        "{%0,%1,%2,%3}, {%4,%5,%6,%7}, {%8,%9}, {%0,%1,%2,%3};"
                        : "+f"(c[mt][nt][0]), "+f"(c[mt][nt][1]),
                          "+f"(c[mt][nt][2]), "+f"(c[mt][nt][3])
                        : "r"(afr[mt][0]), "r"(afr[mt][1]), "r"(afr[mt][2]), "r"(afr[mt][3]),
                          "r"(bfr[nt][0]), "r"(bfr[nt][1]));
        }
    }

    // ---- epilogue ----
    const float* sbias = (const float*)(smem + SM_BIAS);
    const int g = lane >> 2;
    const int q4 = lane & 3;
#pragma unroll
    for (int mt = 0; mt < 4; mt++) {
        const int r0 = m0 + wm + mt * 16 + g;
#pragma unroll
        for (int nt = 0; nt < 4; nt++) {
            const int col = wn + nt * 8 + 2 * q4;
            const float b0 = sbias[col], b1 = sbias[col + 1];
            if (r0 < M) {
                float2 v = make_float2(c[mt][nt][0] + b0, c[mt][nt][1] + b1);
                *reinterpret_cast<float2*>(C + (size_t)r0 * D + col) = v;
            }
            if (r0 + 8 < M) {
                float2 v = make_float2(c[mt][nt][2] + b0, c[mt][nt][3] + b1);
                *reinterpret_cast<float2*>(C + (size_t)(r0 + 8) * D + col) = v;
            }
        }
    }
}

// ----------------------------------------------------------------------------
// CSR gather: H[d] += sum_{j in adj(d)} T[col[j]]. Warp per dst node, lane
// owns a float4 chunk. Register accumulation, single RMW of H per row.
// ----------------------------------------------------------------------------
__global__ __launch_bounds__(256) void gather_add(
    const float* __restrict__ T,
    float* __restrict__ H,
    int N)
{
    const int warp  = (blockIdx.x * blockDim.x + threadIdx.x) >> 5;
    const int nwarp = (gridDim.x * blockDim.x) >> 5;
    const int off   = (threadIdx.x & 31) * 4;

    for (int d = warp; d < N; d += nwarp) {
        const int beg = g_rowptr[d];
        const int end = g_rowptr[d + 1];
        float4 acc = *reinterpret_cast<const float4*>(H + (size_t)d * D + off);
        int j = beg;
        for (; j + 4 <= end; j += 4) {
            const int s0 = g_col[j], s1 = g_col[j + 1];
            const int s2 = g_col[j + 2], s3 = g_col[j + 3];
            const float4 v0 = *reinterpret_cast<const float4*>(T + (size_t)s0 * D + off);
            const float4 v1 = *reinterpret_cast<const float4*>(T + (size_t)s1 * D + off);
            const float4 v2 = *reinterpret_cast<const float4*>(T + (size_t)s2 * D + off);
            const float4 v3 = *reinterpret_cast<const float4*>(T + (size_t)s3 * D + off);
            acc.x += v0.x; acc.y += v0.y; acc.z += v0.z; acc.w += v0.w;
            acc.x += v1.x; acc.y += v1.y; acc.z += v1.z; acc.w += v1.w;
            acc.x += v2.x; acc.y += v2.y; acc.z += v2.z; acc.w += v2.w;
            acc.x += v3.x; acc.y += v3.y; acc.z += v3.z; acc.w += v3.w;
        }
        for (; j < end; j++) {
            const int s = g_col[j];
            const float4 v = *reinterpret_cast<const float4*>(T + (size_t)s * D + off);
            acc.x += v.x; acc.y += v.y; acc.z += v.z; acc.w += v.w;
        }
        *reinterpret_cast<float4*>(H + (size_t)d * D + off) = acc;
    }
}

// ----------------------------------------------------------------------------
// kernel_launch
// Inputs: x, edge_index, W1_rel, b1_rel, W1_root, W2_rel, b2_rel, W2_root
// ----------------------------------------------------------------------------
extern "C" void kernel_launch(void* const* d_in, const int* in_sizes, int n_in,
                              void* d_out, int out_size)
{
    const float* x       = (const float*)d_in[0];
    const void*  ei      = d_in[1];
    const float* W1_rel  = (const float*)d_in[2];
    const float* b1      = (const float*)d_in[3];
    const float* W1_root = (const float*)d_in[4];
    const float* W2_rel  = (const float*)d_in[5];
    const float* b2      = (const float*)d_in[6];
    const float* W2_root = (const float*)d_in[7];
    float*       out     = (float*)d_out;

    const int M = in_sizes[0] / D;   // 20000
    const int E = in_sizes[1] / 2;   // 640000

    void *tptr = nullptr, *hptr = nullptr, *wptr = nullptr;
    cudaGetSymbolAddress(&tptr, g_T);
    cudaGetSymbolAddress(&hptr, g_H);
    cudaGetSymbolAddress(&wptr, g_Wimg);
    float* T = (float*)tptr;
    float* H = (float*)hptr;
    const __nv_bfloat16* Wimg = (const __nv_bfloat16*)wptr;

    cudaFuncSetAttribute(gemm_mma<false>, cudaFuncAttributeMaxDynamicSharedMemorySize, SM_TOTAL);
    cudaFuncSetAttribute(gemm_mma<true>,  cudaFuncAttributeMaxDynamicSharedMemorySize, SM_TOTAL);

    dim3 ggrid((M + 127) / 128, 2);
    const int eblocks = (E + 255) / 256;
    const int nblocks = (M + 255) / 256;
    const int sblocks = (M + SCAN_B - 1) / SCAN_B;

    // CSR build (dst-sorted adjacency)
    init_detect<<<nblocks, 256>>>((const unsigned int*)ei, M);
    hist_dst<<<eblocks, 256>>>(ei, E);
    scan_reduce<<<sblocks, SCAN_B>>>(M);
    scan_top<<<1, 32>>>(sblocks, M, E);
    scan_write<<<sblocks, SCAN_B>>>(M);
    fill_col<<<eblocks, 256>>>(ei, E);
    // weights
    wprep<<<dim3(4, 8), 128>>>(W1_rel, W1_root, W2_rel, W2_root);

    // Layer 1: T = x@W1_rel ; H = x@W1_root + b1 ; H += gather(T)
    gemm_mma<false><<<ggrid, 256, SM_TOTAL>>>(x, Wimg, b1, T, H, M);
    gather_add<<<2500, 256>>>(T, H, M);
    // Layer 2 (ReLU fused into A conversion)
    gemm_mma<true><<<ggrid, 256, SM_TOTAL>>>(H, Wimg + 2 * (2 * D * D), b2, T, out, M);
    gather_add<<<2500, 256>>>(T, out, M);
}